// round 13
// baseline (speedup 1.0000x reference)
#include <cuda_runtime.h>
#include <cstdint>

// out[mu[k], e] += X1[m1[k], e] * X2[m2[k], e] * mult[k]
// M=9, K~100 runtime terms (mu pre-sorted), ND = N*D = 2^20, fp32.
//
// R13: persistent double-buffered kernel, 444 CTAs (3/SM), 256 threads,
// one float2 column per thread over 512-float tiles (24 warps/SM for
// latency hiding; LDS-issue demand stays under the MIO floor at 3 CTAs/SM).
// Self-resetting global ticket (single graph node). Flat padded program
// {off1|off2<<16, mult}; inner loop = unconditional LDS.64 pair + packed
// f32x2 math, unroll-2 with prog prefetch, dual accumulators. No a-reuse
// (carried-register reloads serialize the loop — R12 lesson).

#define M_CH    9
#define TILE    512                    // floats per channel per tile
#define TILE_B  (TILE * 4)             // 2048 B per channel tile
#define BUF_B   (2 * M_CH * TILE_B)    // 36864 B per buffer
#define THREADS 256
#define NCTAS   444                    // 3 per SM x 148
#define MAXK    112
#define PROGMAX 128

__device__ unsigned int g_ticket = 2u * NCTAS;   // self-resetting

struct Smem {
    float4 buf[2][2 * M_CH * (TILE / 4)];  // 73728 B
    int2   prog[PROGMAX];                  // {off1 | off2<<16, mult_bits}
    int    rawmu[MAXK];
    int    seg[16];
    int    pseg[16];
    unsigned long long mbar[2];
    int    next_tk;
};

__device__ __forceinline__ void mbar_wait(uint32_t addr, int parity)
{
    asm volatile(
        "{\n\t.reg .pred P;\n\t"
        "W_%=:\n\t"
        "mbarrier.try_wait.parity.acquire.cta.shared::cta.b64 P, [%0], %1, 0x989680;\n\t"
        "@P bra.uni D_%=;\n\t"
        "bra.uni W_%=;\n\t"
        "D_%=:\n\t}"
        :: "r"(addr), "r"(parity) : "memory");
}

__device__ __forceinline__ void issue_tile_tma(
    uint32_t dst, const float* X1, const float* X2,
    int tile, int nd4, uint32_t mbar_addr)
{
    asm volatile("mbarrier.arrive.expect_tx.shared.b64 _, [%0], %1;"
                 :: "r"(mbar_addr), "r"((uint32_t)BUF_B) : "memory");
    const char* src1 = (const char*)(X1 + (size_t)tile * TILE);
    const char* src2 = (const char*)(X2 + (size_t)tile * TILE);
    const size_t chanstride = (size_t)nd4 * 16;
#pragma unroll
    for (int m = 0; m < M_CH; m++) {
        asm volatile(
            "cp.async.bulk.shared::cta.global.mbarrier::complete_tx::bytes "
            "[%0], [%1], %2, [%3];"
            :: "r"(dst + m * TILE_B), "l"(src1 + m * chanstride),
               "r"((uint32_t)TILE_B), "r"(mbar_addr) : "memory");
        asm volatile(
            "cp.async.bulk.shared::cta.global.mbarrier::complete_tx::bytes "
            "[%0], [%1], %2, [%3];"
            :: "r"(dst + (M_CH + m) * TILE_B), "l"(src2 + m * chanstride),
               "r"((uint32_t)TILE_B), "r"(mbar_addr) : "memory");
    }
}

__global__ void __launch_bounds__(THREADS, 3)
fused_kernel(const float* __restrict__ X1, const float* __restrict__ X2,
             const int* __restrict__ m1, const int* __restrict__ m2,
             const int* __restrict__ mu, const float* __restrict__ mult,
             float* __restrict__ out, int nd4, int K, int ntiles)
{
    extern __shared__ char smem_raw[];
    Smem* s = (Smem*)smem_raw;
    const int t = threadIdx.x;
    const int bid = blockIdx.x;

    const uint32_t mb0  = (uint32_t)__cvta_generic_to_shared(&s->mbar[0]);
    const uint32_t mb1  = (uint32_t)__cvta_generic_to_shared(&s->mbar[1]);
    const uint32_t buf0 = (uint32_t)__cvta_generic_to_shared(&s->buf[0][0]);
    const uint32_t buf1 = (uint32_t)__cvta_generic_to_shared(&s->buf[1][0]);

    // ---- t0: init mbars, fire both initial TMAs immediately ---------------
    int tile      = bid;                 // buf0
    int tile_next = bid + NCTAS;         // buf1
    if (t == 0) {
        asm volatile("mbarrier.init.shared.b64 [%0], %1;"
                     :: "r"(mb0), "r"(1) : "memory");
        asm volatile("mbarrier.init.shared.b64 [%0], %1;"
                     :: "r"(mb1), "r"(1) : "memory");
        asm volatile("fence.proxy.async.shared::cta;" ::: "memory");
        if (tile < ntiles)
            issue_tile_tma(buf0, X1, X2, tile, nd4, mb0);
        if (tile_next < ntiles)
            issue_tile_tma(buf1, X1, X2, tile_next, nd4, mb1);
    }

    // ---- setup (once per persistent CTA, hidden behind first TMA) ---------
    int myMu = 0, myPack = 0, myMult = 0;
    const bool has_term = (t < K);
    if (has_term) {
        myMu   = mu[t];
        myPack = (m1[t] * TILE_B) | ((m2[t] * TILE_B) << 16);
        myMult = __float_as_int(mult[t]);
        s->rawmu[t] = myMu;
    }
    __syncthreads();                     // rawmu + mbar init visible

    if (t < 16) {                        // warp 0: seg + pseg + pads
        int segv = 0;
        if (t <= M_CH) {
            for (int j = 0; j < K; j++) segv += (s->rawmu[j] < t);
            s->seg[t] = segv;
        }
        const unsigned msk = 0xFFFFu;
        int segn = __shfl_down_sync(msk, segv, 1);
        int len  = segn - segv;          // valid lanes 0..8
        int plen = (len + 1) & ~1;
        int x = plen;
#pragma unroll
        for (int d = 1; d < 16; d <<= 1) {
            int y = __shfl_up_sync(msk, x, d);
            if (t >= d) x += y;
        }
        int psegv = x - plen;            // exclusive scan
        if (t <= 8) {
            s->pseg[t] = psegv;
            if (len & 1)
                s->prog[psegv + len] = make_int2(0, 0);   // mult=0 dummy
            if (t == 8) s->pseg[9] = psegv + plen;
        }
    }
    __syncthreads();

    if (has_term) {
        const int pos = s->pseg[myMu] + (t - s->seg[myMu]);
        s->prog[pos] = make_int2(myPack, myMult);
    }
    __syncthreads();

    // ---- persistent pipelined tile loop ------------------------------------
    float2* __restrict__ out2 = (float2*)out;
    const int nd2 = nd4 * 2;
    int cur = 0;
    int ph0 = 0, ph1 = 0;

    while (tile < ntiles) {
        if (t == 0) {                    // grab next ticket early
            unsigned tk = atomicAdd(&g_ticket, 1u);
            if (tk == 2u * NCTAS + (unsigned)ntiles - 1u)
                atomicExch(&g_ticket, 2u * NCTAS);   // last grab: self-reset
            s->next_tk = (int)tk;
        }

        if (cur == 0) { mbar_wait(mb0, ph0); ph0 ^= 1; }
        else          { mbar_wait(mb1, ph1); ph1 ^= 1; }

        const uint32_t colb  = (cur ? buf1 : buf0) + t * 8;
        const uint32_t colb2 = colb + M_CH * TILE_B;
        const int tbase2 = tile * (TILE / 2);
        int kptr = 0;

#pragma unroll
        for (int m = 0; m < M_CH; m++) {
            unsigned long long acc0 = 0ull, acc1 = 0ull;
            const int k1 = s->pseg[m + 1];
            int k = kptr;
            int4 pr = *(const int4*)&s->prog[k];       // prime pipeline
            for (; k < k1; k += 2) {
                const int4 curp = pr;
                pr = *(const int4*)&s->prog[k + 2];    // prefetch (padded)
                {
                    unsigned long long a, b, c2;
                    asm("ld.shared.b64 %0, [%1];"
                        : "=l"(a) : "r"(colb + (curp.x & 0xFFFF)));
                    asm("ld.shared.b64 %0, [%1];"
                        : "=l"(b) : "r"(colb2 + ((unsigned)curp.x >> 16)));
                    asm("mov.b64 %0, {%1, %1};" : "=l"(c2) : "r"(curp.y));
                    asm("mul.rn.f32x2 %0, %1, %2;" : "=l"(b) : "l"(c2), "l"(b));
                    asm("fma.rn.f32x2 %0, %1, %2, %3;"
                        : "=l"(acc0) : "l"(a), "l"(b), "l"(acc0));
                }
                {
                    unsigned long long a, b, c2;
                    asm("ld.shared.b64 %0, [%1];"
                        : "=l"(a) : "r"(colb + (curp.z & 0xFFFF)));
                    asm("ld.shared.b64 %0, [%1];"
                        : "=l"(b) : "r"(colb2 + ((unsigned)curp.z >> 16)));
                    asm("mov.b64 %0, {%1, %1};" : "=l"(c2) : "r"(curp.w));
                    asm("mul.rn.f32x2 %0, %1, %2;" : "=l"(b) : "l"(c2), "l"(b));
                    asm("fma.rn.f32x2 %0, %1, %2, %3;"
                        : "=l"(acc1) : "l"(a), "l"(b), "l"(acc1));
                }
            }
            kptr = k1;
            unsigned long long acc;
            asm("add.rn.f32x2 %0, %1, %2;" : "=l"(acc) : "l"(acc0), "l"(acc1));
            *(unsigned long long*)&out2[(size_t)m * nd2 + tbase2 + t] = acc;
        }

        __syncthreads();                 // buf[cur] free; next_tk visible
        const int tk = s->next_tk;
        if (t == 0 && tk < ntiles)
            issue_tile_tma(cur ? buf1 : buf0, X1, X2, tk, nd4, cur ? mb1 : mb0);

        tile = tile_next;
        tile_next = tk;
        cur ^= 1;
    }
}

extern "C" void kernel_launch(void* const* d_in, const int* in_sizes, int n_in,
                              void* d_out, int out_size)
{
    const float* X1   = (const float*)d_in[0];
    const float* X2   = (const float*)d_in[1];
    const int*   m1   = (const int*)d_in[2];
    const int*   m2   = (const int*)d_in[3];
    const int*   mu   = (const int*)d_in[4];
    const float* mult = (const float*)d_in[5];
    float*       out  = (float*)d_out;

    const int K      = in_sizes[2];
    const int ND     = in_sizes[0] / M_CH;   // N*D
    const int nd4    = ND / 4;
    const int ntiles = ND / TILE;

    const int smem = (int)sizeof(Smem);
    cudaFuncSetAttribute(fused_kernel,
                         cudaFuncAttributeMaxDynamicSharedMemorySize, smem);
    fused_kernel<<<NCTAS, THREADS, smem>>>(X1, X2, m1, m2, mu, mult,
                                           out, nd4, K, ntiles);
}

// round 14
// speedup vs baseline: 1.1142x; 1.1142x over previous
#include <cuda_runtime.h>
#include <cstdint>

// out[mu[k], e] += X1[m1[k], e] * X2[m2[k], e] * mult[k]
// M=9, K~100 runtime terms (mu pre-sorted), ND = N*D = 2^20, fp32.
//
// R14 = R11's kernel (persistent 444 CTAs / 3 per SM, 128 threads, float4
// column per thread, double-buffered TMA over 512-float tiles, flat padded
// program {off1|off2<<16, mult}, unroll-2 + prog prefetch + dual packed
// accumulators) with a STATIC tile schedule:
//   tile_i = bid + i * NCTAS
// -> no reset kernel, no atomics, single deterministic graph node.

#define M_CH    9
#define TILE    512                    // floats per channel per tile
#define TILE_B  (TILE * 4)             // 2048 B per channel tile
#define BUF_B   (2 * M_CH * TILE_B)    // 36864 B per buffer
#define THREADS 128
#define NCTAS   444                    // 3 per SM x 148
#define MAXK    112
#define PROGMAX 128

struct Smem {
    float4 buf[2][2 * M_CH * (TILE / 4)];  // 73728 B
    int2   prog[PROGMAX];                  // {off1 | off2<<16, mult_bits}
    int    rawmu[MAXK];
    int    seg[16];
    int    pseg[16];
    unsigned long long mbar[2];
};

__device__ __forceinline__ void mbar_wait(uint32_t addr, int parity)
{
    asm volatile(
        "{\n\t.reg .pred P;\n\t"
        "W_%=:\n\t"
        "mbarrier.try_wait.parity.acquire.cta.shared::cta.b64 P, [%0], %1, 0x989680;\n\t"
        "@P bra.uni D_%=;\n\t"
        "bra.uni W_%=;\n\t"
        "D_%=:\n\t}"
        :: "r"(addr), "r"(parity) : "memory");
}

__device__ __forceinline__ void issue_tile_tma(
    uint32_t dst, const float* X1, const float* X2,
    int tile, int nd4, uint32_t mbar_addr)
{
    asm volatile("mbarrier.arrive.expect_tx.shared.b64 _, [%0], %1;"
                 :: "r"(mbar_addr), "r"((uint32_t)BUF_B) : "memory");
    const char* src1 = (const char*)(X1 + (size_t)tile * TILE);
    const char* src2 = (const char*)(X2 + (size_t)tile * TILE);
    const size_t chanstride = (size_t)nd4 * 16;
#pragma unroll
    for (int m = 0; m < M_CH; m++) {
        asm volatile(
            "cp.async.bulk.shared::cta.global.mbarrier::complete_tx::bytes "
            "[%0], [%1], %2, [%3];"
            :: "r"(dst + m * TILE_B), "l"(src1 + m * chanstride),
               "r"((uint32_t)TILE_B), "r"(mbar_addr) : "memory");
        asm volatile(
            "cp.async.bulk.shared::cta.global.mbarrier::complete_tx::bytes "
            "[%0], [%1], %2, [%3];"
            :: "r"(dst + (M_CH + m) * TILE_B), "l"(src2 + m * chanstride),
               "r"((uint32_t)TILE_B), "r"(mbar_addr) : "memory");
    }
}

__global__ void __launch_bounds__(THREADS, 3)
fused_kernel(const float* __restrict__ X1, const float* __restrict__ X2,
             const int* __restrict__ m1, const int* __restrict__ m2,
             const int* __restrict__ mu, const float* __restrict__ mult,
             float* __restrict__ out, int nd4, int K, int ntiles)
{
    extern __shared__ char smem_raw[];
    Smem* s = (Smem*)smem_raw;
    const int t = threadIdx.x;
    const int bid = blockIdx.x;

    const uint32_t mb0  = (uint32_t)__cvta_generic_to_shared(&s->mbar[0]);
    const uint32_t mb1  = (uint32_t)__cvta_generic_to_shared(&s->mbar[1]);
    const uint32_t buf0 = (uint32_t)__cvta_generic_to_shared(&s->buf[0][0]);
    const uint32_t buf1 = (uint32_t)__cvta_generic_to_shared(&s->buf[1][0]);

    // ---- t0: init mbars, fire both initial TMAs immediately ---------------
    int tile = bid;                      // buf0; next (bid+NCTAS) -> buf1
    if (t == 0) {
        asm volatile("mbarrier.init.shared.b64 [%0], %1;"
                     :: "r"(mb0), "r"(1) : "memory");
        asm volatile("mbarrier.init.shared.b64 [%0], %1;"
                     :: "r"(mb1), "r"(1) : "memory");
        asm volatile("fence.proxy.async.shared::cta;" ::: "memory");
        if (tile < ntiles)
            issue_tile_tma(buf0, X1, X2, tile, nd4, mb0);
        if (tile + NCTAS < ntiles)
            issue_tile_tma(buf1, X1, X2, tile + NCTAS, nd4, mb1);
    }

    // ---- setup (once per persistent CTA, hidden behind first TMA) ---------
    int myMu = 0, myPack = 0, myMult = 0;
    const bool has_term = (t < K);
    if (has_term) {
        myMu   = mu[t];
        myPack = (m1[t] * TILE_B) | ((m2[t] * TILE_B) << 16);
        myMult = __float_as_int(mult[t]);
        s->rawmu[t] = myMu;
    }
    __syncthreads();                     // rawmu + mbar init visible

    if (t < 16) {                        // warp 0: seg + pseg + pads
        int segv = 0;
        if (t <= M_CH) {
            for (int j = 0; j < K; j++) segv += (s->rawmu[j] < t);
            s->seg[t] = segv;
        }
        const unsigned msk = 0xFFFFu;
        int segn = __shfl_down_sync(msk, segv, 1);
        int len  = segn - segv;          // valid lanes 0..8
        int plen = (len + 1) & ~1;
        int x = plen;
#pragma unroll
        for (int d = 1; d < 16; d <<= 1) {
            int y = __shfl_up_sync(msk, x, d);
            if (t >= d) x += y;
        }
        int psegv = x - plen;            // exclusive scan
        if (t <= 8) {
            s->pseg[t] = psegv;
            if (len & 1)
                s->prog[psegv + len] = make_int2(0, 0);   // mult=0 dummy
            if (t == 8) s->pseg[9] = psegv + plen;
        }
    }
    __syncthreads();

    if (has_term) {
        const int pos = s->pseg[myMu] + (t - s->seg[myMu]);
        s->prog[pos] = make_int2(myPack, myMult);
    }
    __syncthreads();

    // ---- persistent pipelined tile loop (static schedule) ------------------
    float4* __restrict__ out4 = (float4*)out;
    int cur = 0;
    int ph0 = 0, ph1 = 0;

    while (tile < ntiles) {
        if (cur == 0) { mbar_wait(mb0, ph0); ph0 ^= 1; }
        else          { mbar_wait(mb1, ph1); ph1 ^= 1; }

        const uint32_t colb  = (cur ? buf1 : buf0) + t * 16;
        const uint32_t colb2 = colb + M_CH * TILE_B;
        const int tbase4 = tile * (TILE / 4);
        int kptr = 0;

#pragma unroll
        for (int m = 0; m < M_CH; m++) {
            unsigned long long aL0 = 0ull, aH0 = 0ull;
            unsigned long long aL1 = 0ull, aH1 = 0ull;
            const int k1 = s->pseg[m + 1];
            int k = kptr;
            int4 pr = *(const int4*)&s->prog[k];       // prime pipeline
            for (; k < k1; k += 2) {
                const int4 curp = pr;
                pr = *(const int4*)&s->prog[k + 2];    // prefetch (padded)
                {
                    unsigned long long a0, a1, b0, b1, c2;
                    asm("ld.shared.v2.u64 {%0, %1}, [%2];"
                        : "=l"(a0), "=l"(a1) : "r"(colb + (curp.x & 0xFFFF)));
                    asm("ld.shared.v2.u64 {%0, %1}, [%2];"
                        : "=l"(b0), "=l"(b1) : "r"(colb2 + ((unsigned)curp.x >> 16)));
                    asm("mov.b64 %0, {%1, %1};" : "=l"(c2) : "r"(curp.y));
                    asm("mul.rn.f32x2 %0, %1, %2;" : "=l"(b0) : "l"(c2), "l"(b0));
                    asm("mul.rn.f32x2 %0, %1, %2;" : "=l"(b1) : "l"(c2), "l"(b1));
                    asm("fma.rn.f32x2 %0, %1, %2, %3;"
                        : "=l"(aL0) : "l"(a0), "l"(b0), "l"(aL0));
                    asm("fma.rn.f32x2 %0, %1, %2, %3;"
                        : "=l"(aH0) : "l"(a1), "l"(b1), "l"(aH0));
                }
                {
                    unsigned long long a0, a1, b0, b1, c2;
                    asm("ld.shared.v2.u64 {%0, %1}, [%2];"
                        : "=l"(a0), "=l"(a1) : "r"(colb + (curp.z & 0xFFFF)));
                    asm("ld.shared.v2.u64 {%0, %1}, [%2];"
                        : "=l"(b0), "=l"(b1) : "r"(colb2 + ((unsigned)curp.z >> 16)));
                    asm("mov.b64 %0, {%1, %1};" : "=l"(c2) : "r"(curp.w));
                    asm("mul.rn.f32x2 %0, %1, %2;" : "=l"(b0) : "l"(c2), "l"(b0));
                    asm("mul.rn.f32x2 %0, %1, %2;" : "=l"(b1) : "l"(c2), "l"(b1));
                    asm("fma.rn.f32x2 %0, %1, %2, %3;"
                        : "=l"(aL1) : "l"(a0), "l"(b0), "l"(aL1));
                    asm("fma.rn.f32x2 %0, %1, %2, %3;"
                        : "=l"(aH1) : "l"(a1), "l"(b1), "l"(aH1));
                }
            }
            kptr = k1;
            ulonglong2 acc;
            asm("add.rn.f32x2 %0, %1, %2;" : "=l"(acc.x) : "l"(aL0), "l"(aL1));
            asm("add.rn.f32x2 %0, %1, %2;" : "=l"(acc.y) : "l"(aH0), "l"(aH1));
            *(ulonglong2*)&out4[(size_t)m * nd4 + tbase4 + t] = acc;
        }

        __syncthreads();                 // all reads of buf[cur] complete
        const int tile_refill = tile + 2 * NCTAS;
        if (t == 0 && tile_refill < ntiles)
            issue_tile_tma(cur ? buf1 : buf0, X1, X2, tile_refill, nd4,
                           cur ? mb1 : mb0);

        tile += NCTAS;
        cur ^= 1;
    }
}

extern "C" void kernel_launch(void* const* d_in, const int* in_sizes, int n_in,
                              void* d_out, int out_size)
{
    const float* X1   = (const float*)d_in[0];
    const float* X2   = (const float*)d_in[1];
    const int*   m1   = (const int*)d_in[2];
    const int*   m2   = (const int*)d_in[3];
    const int*   mu   = (const int*)d_in[4];
    const float* mult = (const float*)d_in[5];
    float*       out  = (float*)d_out;

    const int K      = in_sizes[2];
    const int ND     = in_sizes[0] / M_CH;   // N*D
    const int nd4    = ND / 4;
    const int ntiles = ND / TILE;

    const int smem = (int)sizeof(Smem);
    cudaFuncSetAttribute(fused_kernel,
                         cudaFuncAttributeMaxDynamicSharedMemorySize, smem);
    fused_kernel<<<NCTAS, THREADS, smem>>>(X1, X2, m1, m2, mu, mult,
                                           out, nd4, K, ntiles);
}